// round 11
// baseline (speedup 1.0000x reference)
#include <cuda_runtime.h>
#include <cstdint>

#define B_  4
#define N_  1024
#define D_  1024
#define H_  16
#define HD_ 64
#define M_  (B_*N_)   // 4096 token rows

// Scratch (device globals — no runtime allocation allowed)
__device__ float g_xn [M_ * D_];        // LayerNorm output        [4096][1024]
__device__ float g_qkv[M_ * 3 * D_];    // QKV projection output   [4096][3072]
__device__ float g_att[M_ * D_];        // attention output        [4096][1024]

// ---------------------------------------------------------------------------
// Helpers. tf32 mma consumes raw fp32 bits (HW reads top 19 bits).
// ldmatrix.b16 on tf32 data: a 16x8 b32 tile viewed as 16x16 b16 gives the
// exact m16k8 tf32 fragment mapping (thread l <- A[l>>2][l&3], +8r, +4c).
// ---------------------------------------------------------------------------
__device__ __forceinline__ void mma_tf32(float* c, const uint32_t* a, const uint32_t* b) {
    asm volatile(
        "mma.sync.aligned.m16n8k8.row.col.f32.tf32.tf32.f32 "
        "{%0,%1,%2,%3}, {%4,%5,%6,%7}, {%8,%9}, {%0,%1,%2,%3};\n"
        : "+f"(c[0]), "+f"(c[1]), "+f"(c[2]), "+f"(c[3])
        : "r"(a[0]), "r"(a[1]), "r"(a[2]), "r"(a[3]), "r"(b[0]), "r"(b[1]));
}

__device__ __forceinline__ void ldsm4(uint32_t* r, uint32_t saddr) {
    asm volatile("ldmatrix.sync.aligned.m8n8.x4.shared.b16 {%0,%1,%2,%3}, [%4];\n"
        : "=r"(r[0]), "=r"(r[1]), "=r"(r[2]), "=r"(r[3]) : "r"(saddr));
}

__device__ __forceinline__ void cp16(void* smem_dst, const void* gmem_src) {
    const uint32_t s = (uint32_t)__cvta_generic_to_shared(smem_dst);
    asm volatile("cp.async.cg.shared.global [%0], [%1], 16;\n" :: "r"(s), "l"(gmem_src));
}
#define CP_COMMIT() asm volatile("cp.async.commit_group;\n" ::: "memory")
#define CP_WAIT(n)  asm volatile("cp.async.wait_group %0;\n" :: "n"(n) : "memory")

__device__ __forceinline__ uint32_t fu(float f) { return __float_as_uint(f); }

// ---------------------------------------------------------------------------
// LayerNorm: one block per token row, 256 threads, float4 per thread
// ---------------------------------------------------------------------------
__global__ __launch_bounds__(256) void ln_kernel(
    const float* __restrict__ x, const float* __restrict__ gamma,
    const float* __restrict__ beta, float* __restrict__ out)
{
    const int row = blockIdx.x;
    const int tid = threadIdx.x;
    const float4 v = reinterpret_cast<const float4*>(x)[row * (D_ / 4) + tid];

    __shared__ float red[8];
    float s = v.x + v.y + v.z + v.w;
#pragma unroll
    for (int o = 16; o > 0; o >>= 1) s += __shfl_xor_sync(0xffffffffu, s, o);
    if ((tid & 31) == 0) red[tid >> 5] = s;
    __syncthreads();
    float tot = 0.f;
#pragma unroll
    for (int i = 0; i < 8; i++) tot += red[i];
    const float mean = tot * (1.0f / D_);

    const float d0 = v.x - mean, d1 = v.y - mean, d2 = v.z - mean, d3 = v.w - mean;
    float sq = d0 * d0 + d1 * d1 + d2 * d2 + d3 * d3;
    __syncthreads();
#pragma unroll
    for (int o = 16; o > 0; o >>= 1) sq += __shfl_xor_sync(0xffffffffu, sq, o);
    if ((tid & 31) == 0) red[tid >> 5] = sq;
    __syncthreads();
    float vt = 0.f;
#pragma unroll
    for (int i = 0; i < 8; i++) vt += red[i];
    const float rstd = rsqrtf(vt * (1.0f / D_) + 1e-5f);

    const float4 g = reinterpret_cast<const float4*>(gamma)[tid];
    const float4 b = reinterpret_cast<const float4*>(beta)[tid];
    float4 o4;
    o4.x = d0 * rstd * g.x + b.x;
    o4.y = d1 * rstd * g.y + b.y;
    o4.z = d2 * rstd * g.z + b.z;
    o4.w = d3 * rstd * g.w + b.w;
    reinterpret_cast<float4*>(out)[row * (D_ / 4) + tid] = o4;
}

// ---------------------------------------------------------------------------
// TF32 tensor-core GEMM: 3-stage cp.async pipeline, K-step 16, ldmatrix A.
// C[M_, NC] = A[M_, 1024] @ W[1024, NC]
// 128x128 block tile, 8 warps (2x4), warp tile 64x32, one barrier per iter.
// ---------------------------------------------------------------------------
#define AS_STRIDE 20
#define BS_STRIDE 136
#define A_STG (128 * AS_STRIDE)     // floats per A stage (2560)
#define B_STG (16 * BS_STRIDE)      // floats per B stage (2176)
#define GEMM_SMEM_BYTES (3 * (A_STG + B_STG) * 4)   // 56832

template <int NC, bool PROJ>
__global__ __launch_bounds__(256) void mma_gemm_kernel(
    const float* __restrict__ A, const float* __restrict__ W,
    float* __restrict__ C, const float* __restrict__ bias,
    const float* __restrict__ resid)
{
    extern __shared__ float sm[];
    float* Asm = sm;                 // 3 stages of [128][20]
    float* Bsm = sm + 3 * A_STG;     // 3 stages of [16][136]

    const int tid  = threadIdx.x;
    const int lane = tid & 31;
    const int warp = tid >> 5;
    const int wm = (warp >> 2) * 64;
    const int wn = (warp & 3) * 32;
    const int l4 = lane & 3, l8 = lane >> 2;

    const int rb = blockIdx.y * 128;
    const int cb = blockIdx.x * 128;

    // ldmatrix lane address components for A fragments
    const uint32_t as_b = (uint32_t)__cvta_generic_to_shared(Asm);
    uint32_t a_addr[4];
#pragma unroll
    for (int mi = 0; mi < 4; mi++)
        a_addr[mi] = as_b + 4 * ((wm + mi * 16 + (lane & 15)) * AS_STRIDE
                                 + ((lane >> 4) << 2));

    float c[4][4][4];
#pragma unroll
    for (int mi = 0; mi < 4; mi++)
#pragma unroll
        for (int ni = 0; ni < 4; ni++)
#pragma unroll
            for (int j = 0; j < 4; j++) c[mi][ni][j] = 0.f;

    auto issue_tile = [&](int k0, int st) {
#pragma unroll
        for (int i = 0; i < 2; i++) {
            const int f = tid + i * 256;          // 512 float4 slots each
            cp16(Asm + st * A_STG + (f >> 2) * AS_STRIDE + (f & 3) * 4,
                 A + (size_t)(rb + (f >> 2)) * D_ + k0 + (f & 3) * 4);
            cp16(Bsm + st * B_STG + (f >> 5) * BS_STRIDE + (f & 31) * 4,
                 W + (size_t)(k0 + (f >> 5)) * NC + cb + (f & 31) * 4);
        }
        CP_COMMIT();
    };

    issue_tile(0, 0);
    issue_tile(16, 1);

    for (int it = 0; it < 64; ++it) {
        const int st = it % 3;
        // Tail fix: at it==63 ALL groups must be complete (wait_group 1 would
        // allow the stage-63 group itself to still be in flight).
        if (it < 63) { CP_WAIT(1); }
        else         { CP_WAIT(0); }
        __syncthreads();       // all threads' stage-`it` data visible
        if (it < 62) issue_tile((it + 2) * 16, (it + 2) % 3);

        const float* Bb = Bsm + st * B_STG;
        const uint32_t a_off = st * (A_STG * 4);
#pragma unroll
        for (int ks = 0; ks < 16; ks += 8) {
            uint32_t a[4][4], b[4][2];
#pragma unroll
            for (int mi = 0; mi < 4; mi++)
                ldsm4(a[mi], a_addr[mi] + a_off + ks * 4);
#pragma unroll
            for (int ni = 0; ni < 4; ni++) {
                const int cc = wn + ni * 8 + l8;
                b[ni][0] = fu(Bb[(ks + l4) * BS_STRIDE + cc]);
                b[ni][1] = fu(Bb[(ks + 4 + l4) * BS_STRIDE + cc]);
            }
#pragma unroll
            for (int mi = 0; mi < 4; mi++)
#pragma unroll
                for (int ni = 0; ni < 4; ni++)
                    mma_tf32(c[mi][ni], a[mi], b[ni]);
        }
    }

#pragma unroll
    for (int mi = 0; mi < 4; mi++) {
        const int r0 = rb + wm + mi * 16 + l8;
#pragma unroll
        for (int ni = 0; ni < 4; ni++) {
            const int col = cb + wn + ni * 8 + l4 * 2;
            float2 v0 = {c[mi][ni][0], c[mi][ni][1]};
            float2 v1 = {c[mi][ni][2], c[mi][ni][3]};
            if (PROJ) {
                const float2 bz = *reinterpret_cast<const float2*>(bias + col);
                const float2 r0x = *reinterpret_cast<const float2*>(resid + (size_t)r0 * D_ + col);
                const float2 r1x = *reinterpret_cast<const float2*>(resid + (size_t)(r0 + 8) * D_ + col);
                v0.x += bz.x + r0x.x; v0.y += bz.y + r0x.y;
                v1.x += bz.x + r1x.x; v1.y += bz.y + r1x.y;
            }
            *reinterpret_cast<float2*>(C + (size_t)r0 * NC + col) = v0;
            *reinterpret_cast<float2*>(C + (size_t)(r0 + 8) * NC + col) = v1;
        }
    }
}

// ---------------------------------------------------------------------------
// TF32 mma flash attention, cp.async pipelined, ldmatrix fragments.
// Block = 128 q-rows of one (b,h); 8 warps, warp = 16 q-rows; 8 key tiles.
// Q/P a-frags + K b-frags via ldmatrix (tf32-as-b16); V b-frags scalar.
// ---------------------------------------------------------------------------
#define ATT_QS 0                      // [128][68]
#define ATT_KS 8704                   // 2 x [128][68]
#define ATT_KSZ 8704
#define ATT_VS 26112                  // [128][72]
#define ATT_PS 35328                  // [128][132]
#define ATT_SMEM_BYTES ((35328 + 128 * 132) * 4)   // 208896 B

__global__ __launch_bounds__(256, 1) void attn_mma_kernel(
    const float* __restrict__ qkv, const float* __restrict__ sim,
    const float* __restrict__ swlp, float* __restrict__ att)
{
    extern __shared__ float sm[];
    float* Qs = sm + ATT_QS;
    float* Ks = sm + ATT_KS;
    float* Vs = sm + ATT_VS;
    float* Ps = sm + ATT_PS;

    const int tid  = threadIdx.x;
    const int lane = tid & 31, warp = tid >> 5;
    const int l4 = lane & 3, l8 = lane >> 2;
    const int wm = warp * 16;
    const int qb = blockIdx.x * 128;
    const int b  = blockIdx.y >> 4, h = blockIdx.y & 15;

    const float alpha = 1.f / (1.f + __expf(-(*swlp)));
    const float c1 = (1.f - alpha) * 0.125f;
    const float c2 = alpha;

    const float* qp    = qkv + (size_t)(b * N_ + qb) * 3 * D_ + h * HD_;
    const float* kbase = qkv + (size_t)(b * N_) * 3 * D_ + D_ + h * HD_;
    const float* vbase = qkv + (size_t)(b * N_) * 3 * D_ + 2 * D_ + h * HD_;

    // ldmatrix lane addresses
    const uint32_t smb = (uint32_t)__cvta_generic_to_shared(sm);
    const uint32_t q_ld = smb + ATT_QS * 4
        + 4 * ((wm + (lane & 15)) * 68 + ((lane >> 4) << 2));
    // K b-frag pair (ni=2j, 2j+1): row = j*16 + ((lane>>4)<<3) + (lane&7),
    // b32 col = ((lane>>3)&1)*4 (+ks)
    const uint32_t k_ln = 4 * (((((lane >> 4) << 3) + (lane & 7))) * 68
                               + (((lane >> 3) & 1) << 2));
    const uint32_t p_ld = smb + ATT_PS * 4
        + 4 * ((wm + (lane & 15)) * 132 + ((lane >> 4) << 2));

    // Prologue: Q tile + K(0) via cp.async (one group)
#pragma unroll
    for (int i = 0; i < 8; i++) {
        const int idx = tid + i * 256;            // 2048 float4 slots
        const int r = idx >> 4, c4 = (idx & 15) * 4;
        cp16(&Qs[r * 68 + c4], qp + (size_t)r * 3 * D_ + c4);
        cp16(&Ks[r * 68 + c4], kbase + (size_t)r * 3 * D_ + c4);
    }
    CP_COMMIT();

    float o[8][4];
#pragma unroll
    for (int ni = 0; ni < 8; ni++)
#pragma unroll
        for (int j = 0; j < 4; j++) o[ni][j] = 0.f;
    float m0 = -1e30f, m1 = -1e30f, l0 = 0.f, l1 = 0.f;

    for (int t = 0; t < 8; t++) {
        const int kb = t * 128;
        const uint32_t kt_addr = smb + (ATT_KS + (t & 1) * ATT_KSZ) * 4 + k_ln;

        __syncthreads();   // all warps done with Vs (prev P@V)

        // Issue V(t) — overlaps with S-mma below
#pragma unroll
        for (int i = 0; i < 8; i++) {
            const int idx = tid + i * 256;
            const int r = idx >> 4, c4 = (idx & 15) * 4;
            cp16(&Vs[r * 72 + c4], vbase + (size_t)(kb + r) * 3 * D_ + c4);
        }
        CP_COMMIT();

        CP_WAIT(1);        // K(t) [+Q] complete; V(t) still in flight
        __syncthreads();

        // ---- S = Q @ K^T : 16 n-frags, k = 64, ldmatrix everywhere ----
        float s[16][4];
#pragma unroll
        for (int ni = 0; ni < 16; ni++)
#pragma unroll
            for (int j = 0; j < 4; j++) s[ni][j] = 0.f;
#pragma unroll
        for (int ks = 0; ks < 64; ks += 8) {
            uint32_t a[4];
            ldsm4(a, q_ld + ks * 4);
#pragma unroll
            for (int j = 0; j < 8; j++) {
                uint32_t bb[4];
                ldsm4(bb, kt_addr + j * 4352 + ks * 4);   // 4352 = 16*68*4
                mma_tf32(s[2 * j],     a, bb);
                mma_tf32(s[2 * j + 1], a, bb + 2);
            }
        }

        // Prefetch K(t+1) into other buffer — overlaps softmax + P@V
        if (t < 7) {
            float* Kn = Ks + ((t + 1) & 1) * ATT_KSZ;
#pragma unroll
            for (int i = 0; i < 8; i++) {
                const int idx = tid + i * 256;
                const int r = idx >> 4, c4 = (idx & 15) * 4;
                cp16(&Kn[r * 68 + c4], kbase + (size_t)(kb + 128 + r) * 3 * D_ + c4);
            }
            CP_COMMIT();
            CP_WAIT(1);    // V(t) complete; K(t+1) in flight
        } else {
            CP_WAIT(0);
        }
        __syncthreads();   // Vs visible to all warps

        // ---- blend with sim (L2-resident gmem) + online softmax ----
        const float* simp = sim + (size_t)(qb + wm + l8) * N_ + kb;
        float zx0 = -1e30f, zx1 = -1e30f;
#pragma unroll
        for (int ni = 0; ni < 16; ni++) {
            const float2 s0 = __ldg(reinterpret_cast<const float2*>(simp + ni * 8 + l4 * 2));
            const float2 s1 = __ldg(reinterpret_cast<const float2*>(simp + 8 * N_ + ni * 8 + l4 * 2));
            s[ni][0] = fmaf(s[ni][0], c1, s0.x * c2);
            s[ni][1] = fmaf(s[ni][1], c1, s0.y * c2);
            s[ni][2] = fmaf(s[ni][2], c1, s1.x * c2);
            s[ni][3] = fmaf(s[ni][3], c1, s1.y * c2);
            zx0 = fmaxf(zx0, fmaxf(s[ni][0], s[ni][1]));
            zx1 = fmaxf(zx1, fmaxf(s[ni][2], s[ni][3]));
        }
        zx0 = fmaxf(zx0, __shfl_xor_sync(0xffffffffu, zx0, 1));
        zx0 = fmaxf(zx0, __shfl_xor_sync(0xffffffffu, zx0, 2));
        zx1 = fmaxf(zx1, __shfl_xor_sync(0xffffffffu, zx1, 1));
        zx1 = fmaxf(zx1, __shfl_xor_sync(0xffffffffu, zx1, 2));

        const float mn0 = fmaxf(m0, zx0), mn1 = fmaxf(m1, zx1);
        const float f0 = __expf(m0 - mn0), f1 = __expf(m1 - mn1);
        m0 = mn0; m1 = mn1;

        float ls0 = 0.f, ls1 = 0.f;
        float* prow0 = Ps + (wm + l8) * 132;
        float* prow1 = Ps + (wm + l8 + 8) * 132;
#pragma unroll
        for (int ni = 0; ni < 16; ni++) {
            const float p0 = __expf(s[ni][0] - mn0);
            const float p1 = __expf(s[ni][1] - mn0);
            const float p2 = __expf(s[ni][2] - mn1);
            const float p3 = __expf(s[ni][3] - mn1);
            ls0 += p0 + p1; ls1 += p2 + p3;
            *reinterpret_cast<float2*>(prow0 + ni * 8 + l4 * 2) = make_float2(p0, p1);
            *reinterpret_cast<float2*>(prow1 + ni * 8 + l4 * 2) = make_float2(p2, p3);
        }
        ls0 += __shfl_xor_sync(0xffffffffu, ls0, 1);
        ls0 += __shfl_xor_sync(0xffffffffu, ls0, 2);
        ls1 += __shfl_xor_sync(0xffffffffu, ls1, 1);
        ls1 += __shfl_xor_sync(0xffffffffu, ls1, 2);
        l0 = l0 * f0 + ls0;
        l1 = l1 * f1 + ls1;

#pragma unroll
        for (int ni = 0; ni < 8; ni++) {
            o[ni][0] *= f0; o[ni][1] *= f0;
            o[ni][2] *= f1; o[ni][3] *= f1;
        }
        __syncwarp();   // P rows warp-private: order stores before ldmatrix

        // ---- O += P @ V : 8 n-frags, k = 128; ldmatrix a, scalar V b ----
#pragma unroll
        for (int ks = 0; ks < 128; ks += 8) {
            uint32_t a[4];
            ldsm4(a, p_ld + ks * 4);
#pragma unroll
            for (int ni = 0; ni < 8; ni++) {
                uint32_t bf[2];
                bf[0] = fu(Vs[(ks + l4) * 72 + ni * 8 + l8]);
                bf[1] = fu(Vs[(ks + 4 + l4) * 72 + ni * 8 + l8]);
                mma_tf32(o[ni], a, bf);
            }
        }
    }

    // Epilogue: normalize and store
    const float inv0 = 1.f / l0, inv1 = 1.f / l1;
    float* op0 = att + (size_t)(b * N_ + qb + wm + l8) * D_ + h * HD_;
    float* op1 = op0 + 8 * D_;
#pragma unroll
    for (int ni = 0; ni < 8; ni++) {
        float2 v0 = {o[ni][0] * inv0, o[ni][1] * inv0};
        float2 v1 = {o[ni][2] * inv1, o[ni][3] * inv1};
        *reinterpret_cast<float2*>(op0 + ni * 8 + l4 * 2) = v0;
        *reinterpret_cast<float2*>(op1 + ni * 8 + l4 * 2) = v1;
    }
}

// ---------------------------------------------------------------------------
extern "C" void kernel_launch(void* const* d_in, const int* in_sizes, int n_in,
                              void* d_out, int out_size)
{
    const float* x      = (const float*)d_in[0];
    const float* gamma  = (const float*)d_in[1];
    const float* beta   = (const float*)d_in[2];
    const float* w_qkv  = (const float*)d_in[3];
    const float* w_proj = (const float*)d_in[4];
    const float* b_proj = (const float*)d_in[5];
    const float* swl    = (const float*)d_in[6];
    const float* sim    = (const float*)d_in[7];
    float* out = (float*)d_out;

    float *xn, *qkvb, *attb;
    cudaGetSymbolAddress((void**)&xn,   g_xn);
    cudaGetSymbolAddress((void**)&qkvb, g_qkv);
    cudaGetSymbolAddress((void**)&attb, g_att);

    // 1. LayerNorm
    ln_kernel<<<M_, 256>>>(x, gamma, beta, xn);

    // 2. QKV projection (tf32 mma, 3-stage cp.async, ldmatrix)
    cudaFuncSetAttribute(mma_gemm_kernel<3 * D_, false>,
                         cudaFuncAttributeMaxDynamicSharedMemorySize,
                         GEMM_SMEM_BYTES);
    mma_gemm_kernel<3 * D_, false><<<dim3(24, 32), 256, GEMM_SMEM_BYTES>>>(
        xn, w_qkv, qkvb, nullptr, nullptr);

    // 3. Attention (flash, tf32 mma, cp.async, ldmatrix)
    cudaFuncSetAttribute(attn_mma_kernel,
                         cudaFuncAttributeMaxDynamicSharedMemorySize,
                         ATT_SMEM_BYTES);
    attn_mma_kernel<<<dim3(8, 64), 256, ATT_SMEM_BYTES>>>(qkvb, sim, swl, attb);

    // 4. Output projection + bias + residual -> d_out
    cudaFuncSetAttribute(mma_gemm_kernel<D_, true>,
                         cudaFuncAttributeMaxDynamicSharedMemorySize,
                         GEMM_SMEM_BYTES);
    mma_gemm_kernel<D_, true><<<dim3(8, 32), 256, GEMM_SMEM_BYTES>>>(
        attb, w_proj, out, b_proj, x);
}

// round 12
// speedup vs baseline: 1.1163x; 1.1163x over previous
#include <cuda_runtime.h>
#include <cuda_bf16.h>
#include <cstdint>

#define B_  4
#define N_  1024
#define D_  1024
#define H_  16
#define HD_ 64
#define M_  (B_*N_)   // 4096 token rows

// Scratch (device globals — no runtime allocation allowed)
__device__ __nv_bfloat16 g_xn  [M_ * D_];        // LN output (bf16 GEMM A)
__device__ __nv_bfloat16 g_qkv [M_ * 3 * D_];    // QKV output (bf16)
__device__ __nv_bfloat16 g_att [M_ * D_];        // attention output (bf16)
__device__ __nv_bfloat16 g_wqkv[D_ * 3 * D_];    // w_qkv bf16
__device__ __nv_bfloat16 g_wprj[D_ * D_];        // w_proj bf16

// ---------------------------------------------------------------------------
// Helpers
// ---------------------------------------------------------------------------
__device__ __forceinline__ void mma_bf16(float* c, const uint32_t* a, const uint32_t* b) {
    asm volatile(
        "mma.sync.aligned.m16n8k16.row.col.f32.bf16.bf16.f32 "
        "{%0,%1,%2,%3}, {%4,%5,%6,%7}, {%8,%9}, {%0,%1,%2,%3};\n"
        : "+f"(c[0]), "+f"(c[1]), "+f"(c[2]), "+f"(c[3])
        : "r"(a[0]), "r"(a[1]), "r"(a[2]), "r"(a[3]), "r"(b[0]), "r"(b[1]));
}

__device__ __forceinline__ void ldsm4(uint32_t* r, uint32_t saddr) {
    asm volatile("ldmatrix.sync.aligned.m8n8.x4.shared.b16 {%0,%1,%2,%3}, [%4];\n"
        : "=r"(r[0]), "=r"(r[1]), "=r"(r[2]), "=r"(r[3]) : "r"(saddr));
}
__device__ __forceinline__ void ldsm4t(uint32_t* r, uint32_t saddr) {
    asm volatile("ldmatrix.sync.aligned.m8n8.x4.trans.shared.b16 {%0,%1,%2,%3}, [%4];\n"
        : "=r"(r[0]), "=r"(r[1]), "=r"(r[2]), "=r"(r[3]) : "r"(saddr));
}

__device__ __forceinline__ void cp16(void* smem_dst, const void* gmem_src) {
    const uint32_t s = (uint32_t)__cvta_generic_to_shared(smem_dst);
    asm volatile("cp.async.cg.shared.global [%0], [%1], 16;\n" :: "r"(s), "l"(gmem_src));
}
#define CP_COMMIT() asm volatile("cp.async.commit_group;\n" ::: "memory")
#define CP_WAIT(n)  asm volatile("cp.async.wait_group %0;\n" :: "n"(n) : "memory")

__device__ __forceinline__ uint32_t pack_bf2(float a, float b) {
    __nv_bfloat162 h = __float22bfloat162_rn(make_float2(a, b));
    return *reinterpret_cast<uint32_t*>(&h);
}

// ---------------------------------------------------------------------------
// fp32 -> bf16 weight conversion (grid-stride over float4)
// ---------------------------------------------------------------------------
__global__ __launch_bounds__(256) void cvt_kernel(
    const float* __restrict__ src, __nv_bfloat16* __restrict__ dst, int n4)
{
    const int i = blockIdx.x * blockDim.x + threadIdx.x;
    if (i < n4) {
        const float4 v = reinterpret_cast<const float4*>(src)[i];
        uint2 u;
        u.x = pack_bf2(v.x, v.y);
        u.y = pack_bf2(v.z, v.w);
        reinterpret_cast<uint2*>(dst)[i] = u;
    }
}

// ---------------------------------------------------------------------------
// LayerNorm: one block per row, 256 threads, float4 in -> bf16x4 out
// ---------------------------------------------------------------------------
__global__ __launch_bounds__(256) void ln_kernel(
    const float* __restrict__ x, const float* __restrict__ gamma,
    const float* __restrict__ beta, __nv_bfloat16* __restrict__ out)
{
    const int row = blockIdx.x;
    const int tid = threadIdx.x;
    const float4 v = reinterpret_cast<const float4*>(x)[row * (D_ / 4) + tid];

    __shared__ float red[8];
    float s = v.x + v.y + v.z + v.w;
#pragma unroll
    for (int o = 16; o > 0; o >>= 1) s += __shfl_xor_sync(0xffffffffu, s, o);
    if ((tid & 31) == 0) red[tid >> 5] = s;
    __syncthreads();
    float tot = 0.f;
#pragma unroll
    for (int i = 0; i < 8; i++) tot += red[i];
    const float mean = tot * (1.0f / D_);

    const float d0 = v.x - mean, d1 = v.y - mean, d2 = v.z - mean, d3 = v.w - mean;
    float sq = d0 * d0 + d1 * d1 + d2 * d2 + d3 * d3;
    __syncthreads();
#pragma unroll
    for (int o = 16; o > 0; o >>= 1) sq += __shfl_xor_sync(0xffffffffu, sq, o);
    if ((tid & 31) == 0) red[tid >> 5] = sq;
    __syncthreads();
    float vt = 0.f;
#pragma unroll
    for (int i = 0; i < 8; i++) vt += red[i];
    const float rstd = rsqrtf(vt * (1.0f / D_) + 1e-5f);

    const float4 g = reinterpret_cast<const float4*>(gamma)[tid];
    const float4 b = reinterpret_cast<const float4*>(beta)[tid];
    uint2 u;
    u.x = pack_bf2(d0 * rstd * g.x + b.x, d1 * rstd * g.y + b.y);
    u.y = pack_bf2(d2 * rstd * g.z + b.z, d3 * rstd * g.w + b.w);
    reinterpret_cast<uint2*>(out)[row * (D_ / 4) + tid] = u;
}

// ---------------------------------------------------------------------------
// BF16 tensor-core GEMM, cp.async double buffer (R7 control flow).
// C[M_, NC] = A[M_, 1024] @ W[1024, NC], A/W bf16.
// 128x128 block tile, K-step 32, 8 warps (2x4), warp tile 64x32.
// A smem [128][40] bf16 (pitch 80 B); B smem [32][136] bf16 (pitch 272 B).
// PROJ: C fp32 += bias + resid.  !PROJ: C bf16.
// ---------------------------------------------------------------------------
#define GA_PITCH 40
#define GB_PITCH 136
#define GA_STG_BYTES (128 * GA_PITCH * 2)   // 10240
#define GB_STG_BYTES (32 * GB_PITCH * 2)    // 8704

template <int NC, bool PROJ>
__global__ __launch_bounds__(256) void bf16_gemm_kernel(
    const __nv_bfloat16* __restrict__ A, const __nv_bfloat16* __restrict__ W,
    void* __restrict__ Cv, const float* __restrict__ bias,
    const float* __restrict__ resid)
{
    __shared__ __nv_bfloat16 As[2][128 * GA_PITCH];
    __shared__ __nv_bfloat16 Bs[2][32 * GB_PITCH];

    const int tid  = threadIdx.x;
    const int lane = tid & 31;
    const int warp = tid >> 5;
    const int wm = (warp >> 2) * 64;
    const int wn = (warp & 3) * 32;
    const int l4 = lane & 3, l8 = lane >> 2;

    const int rb = blockIdx.y * 128;
    const int cb = blockIdx.x * 128;

    // ldmatrix lane addresses (bytes)
    const uint32_t as_b = (uint32_t)__cvta_generic_to_shared(&As[0][0]);
    const uint32_t bs_b = (uint32_t)__cvta_generic_to_shared(&Bs[0][0]);
    uint32_t a_addr[4];
#pragma unroll
    for (int mi = 0; mi < 4; mi++)
        a_addr[mi] = as_b + ((wm + mi * 16 + (lane & 15)) * GA_PITCH
                             + ((lane >> 4) & 1) * 8) * 2;
    const uint32_t b_addr = bs_b
        + ((((lane & 7) + ((lane >> 3) & 1) * 8)) * GB_PITCH
           + ((lane >> 4) & 1) * 8 + wn) * 2;

    float c[4][4][4];
#pragma unroll
    for (int mi = 0; mi < 4; mi++)
#pragma unroll
        for (int ni = 0; ni < 4; ni++)
#pragma unroll
            for (int j = 0; j < 4; j++) c[mi][ni][j] = 0.f;

    auto issue_tile = [&](int k0, int st) {
#pragma unroll
        for (int i = 0; i < 2; i++) {
            const int f = tid + i * 256;          // 512 16B chunks each
            cp16(&As[st][(f >> 2) * GA_PITCH + (f & 3) * 8],
                 A + (size_t)(rb + (f >> 2)) * D_ + k0 + (f & 3) * 8);
            cp16(&Bs[st][(f >> 4) * GB_PITCH + (f & 15) * 8],
                 W + (size_t)(k0 + (f >> 4)) * NC + cb + (f & 15) * 8);
        }
        CP_COMMIT();
    };

    issue_tile(0, 0);
    for (int it = 0; it < 32; ++it) {
        const int buf = it & 1;
        if (it < 31) { issue_tile((it + 1) * 32, buf ^ 1); CP_WAIT(1); }
        else         { CP_WAIT(0); }
        __syncthreads();

        const uint32_t ao = (uint32_t)buf * GA_STG_BYTES;
        const uint32_t bo = (uint32_t)buf * GB_STG_BYTES;
#pragma unroll
        for (int ks = 0; ks < 32; ks += 16) {
            uint32_t a[4][4], bb[2][4];
#pragma unroll
            for (int mi = 0; mi < 4; mi++)
                ldsm4(a[mi], a_addr[mi] + ao + ks * 2);
#pragma unroll
            for (int np = 0; np < 2; np++)
                ldsm4t(bb[np], b_addr + bo + ks * (GB_PITCH * 2) + np * 32);
#pragma unroll
            for (int mi = 0; mi < 4; mi++)
#pragma unroll
                for (int np = 0; np < 2; np++) {
                    mma_bf16(c[mi][2 * np],     a[mi], bb[np]);
                    mma_bf16(c[mi][2 * np + 1], a[mi], bb[np] + 2);
                }
        }
        __syncthreads();
    }

#pragma unroll
    for (int mi = 0; mi < 4; mi++) {
        const int r0 = rb + wm + mi * 16 + l8;
#pragma unroll
        for (int ni = 0; ni < 4; ni++) {
            const int col = cb + wn + ni * 8 + l4 * 2;
            if (PROJ) {
                float* C = (float*)Cv;
                float2 v0 = {c[mi][ni][0], c[mi][ni][1]};
                float2 v1 = {c[mi][ni][2], c[mi][ni][3]};
                const float2 bz = *reinterpret_cast<const float2*>(bias + col);
                const float2 r0x = *reinterpret_cast<const float2*>(resid + (size_t)r0 * D_ + col);
                const float2 r1x = *reinterpret_cast<const float2*>(resid + (size_t)(r0 + 8) * D_ + col);
                v0.x += bz.x + r0x.x; v0.y += bz.y + r0x.y;
                v1.x += bz.x + r1x.x; v1.y += bz.y + r1x.y;
                *reinterpret_cast<float2*>(C + (size_t)r0 * NC + col) = v0;
                *reinterpret_cast<float2*>(C + (size_t)(r0 + 8) * NC + col) = v1;
            } else {
                __nv_bfloat16* C = (__nv_bfloat16*)Cv;
                *reinterpret_cast<uint32_t*>(C + (size_t)r0 * NC + col)
                    = pack_bf2(c[mi][ni][0], c[mi][ni][1]);
                *reinterpret_cast<uint32_t*>(C + (size_t)(r0 + 8) * NC + col)
                    = pack_bf2(c[mi][ni][2], c[mi][ni][3]);
            }
        }
    }
}

// ---------------------------------------------------------------------------
// BF16 mma flash attention (R11 pipeline structure, bf16 data path).
// Block = 128 q-rows of one (b,h); 8 warps x 16 q-rows; 8 key tiles of 128.
// Q/K/V/P bf16 in smem; S and O accumulate fp32; P@V via m16n8k16.
// Smem (bytes): Qs [128][72] @0 | Ks 2x[128][72] @18432 | Vs [128][72] @55296
//               Ps [128][136] @73728 ; total 108544.
// ---------------------------------------------------------------------------
#define AQ_BYTE 0
#define AK_BYTE 18432
#define AK_STG  18432
#define AV_BYTE 55296
#define AP_BYTE 73728
#define ATT_SMEM_BYTES 108544

__global__ __launch_bounds__(256, 1) void attn_bf16_kernel(
    const __nv_bfloat16* __restrict__ qkv, const float* __restrict__ sim,
    const float* __restrict__ swlp, __nv_bfloat16* __restrict__ att)
{
    extern __shared__ char smc[];
    __nv_bfloat16* Qs = (__nv_bfloat16*)(smc + AQ_BYTE);   // pitch 72
    __nv_bfloat16* Ks = (__nv_bfloat16*)(smc + AK_BYTE);   // pitch 72, 2 stages
    __nv_bfloat16* Vs = (__nv_bfloat16*)(smc + AV_BYTE);   // pitch 72
    __nv_bfloat16* Ps = (__nv_bfloat16*)(smc + AP_BYTE);   // pitch 136

    const int tid  = threadIdx.x;
    const int lane = tid & 31, warp = tid >> 5;
    const int l4 = lane & 3, l8 = lane >> 2;
    const int wm = warp * 16;
    const int qb = blockIdx.x * 128;
    const int b  = blockIdx.y >> 4, h = blockIdx.y & 15;

    const float alpha = 1.f / (1.f + __expf(-(*swlp)));
    const float c1 = (1.f - alpha) * 0.125f;
    const float c2 = alpha;

    const __nv_bfloat16* qp    = qkv + (size_t)(b * N_ + qb) * 3 * D_ + h * HD_;
    const __nv_bfloat16* kbase = qkv + (size_t)(b * N_) * 3 * D_ + D_ + h * HD_;
    const __nv_bfloat16* vbase = qkv + (size_t)(b * N_) * 3 * D_ + 2 * D_ + h * HD_;

    // ldmatrix lane addresses (bytes)
    const uint32_t smb = (uint32_t)__cvta_generic_to_shared(smc);
    const uint32_t q_ld = smb + AQ_BYTE
        + ((wm + (lane & 15)) * 72 + ((lane >> 4) & 1) * 8) * 2;
    // K b-frags (non-trans; natural [key][d] IS the B layout):
    // row = j*16 + ((lane>>4)&1)*8 + (lane&7), col = ks + ((lane>>3)&1)*8
    const uint32_t k_ln = smb + AK_BYTE
        + ((((lane >> 4) & 1) * 8 + (lane & 7)) * 72 + ((lane >> 3) & 1) * 8) * 2;
    const uint32_t p_ld = smb + AP_BYTE
        + ((wm + (lane & 15)) * 136 + ((lane >> 4) & 1) * 8) * 2;
    // V b-frags (trans; [k][n] rows): row = ks + (l&7) + ((l>>3)&1)*8,
    // col = np*16 + ((l>>4)&1)*8
    const uint32_t v_ln = smb + AV_BYTE
        + (((lane & 7) + ((lane >> 3) & 1) * 8) * 72 + ((lane >> 4) & 1) * 8) * 2;

    // Prologue: Q tile + K(0) via cp.async (one group). 128B/row = 8 chunks.
#pragma unroll
    for (int i = 0; i < 4; i++) {
        const int idx = tid + i * 256;            // 1024 chunks
        const int r = idx >> 3, c8 = (idx & 7) * 8;
        cp16(&Qs[r * 72 + c8], qp + (size_t)r * 3 * D_ + c8);
        cp16(&Ks[r * 72 + c8], kbase + (size_t)r * 3 * D_ + c8);
    }
    CP_COMMIT();

    float o[8][4];
#pragma unroll
    for (int ni = 0; ni < 8; ni++)
#pragma unroll
        for (int j = 0; j < 4; j++) o[ni][j] = 0.f;
    float m0 = -1e30f, m1 = -1e30f, l0 = 0.f, l1 = 0.f;

    for (int t = 0; t < 8; t++) {
        const int kb = t * 128;
        const uint32_t kst = k_ln + (t & 1) * AK_STG;

        __syncthreads();   // all warps done with Vs (prev P@V)

        // Issue V(t) — overlaps with S-mma below
#pragma unroll
        for (int i = 0; i < 4; i++) {
            const int idx = tid + i * 256;
            const int r = idx >> 3, c8 = (idx & 7) * 8;
            cp16(&Vs[r * 72 + c8], vbase + (size_t)(kb + r) * 3 * D_ + c8);
        }
        CP_COMMIT();

        CP_WAIT(1);        // K(t) [+Q] complete; V(t) still in flight
        __syncthreads();

        // ---- S = Q @ K^T : 16 n-frags, k = 64 (4 ksteps of 16) ----
        float s[16][4];
#pragma unroll
        for (int ni = 0; ni < 16; ni++)
#pragma unroll
            for (int j = 0; j < 4; j++) s[ni][j] = 0.f;
#pragma unroll
        for (int ks = 0; ks < 64; ks += 16) {
            uint32_t a[4];
            ldsm4(a, q_ld + ks * 2);
#pragma unroll
            for (int j = 0; j < 8; j++) {
                uint32_t bb[4];
                ldsm4(bb, kst + j * 2304 + ks * 2);   // 2304 = 16*72*2
                mma_bf16(s[2 * j],     a, bb);
                mma_bf16(s[2 * j + 1], a, bb + 2);
            }
        }

        // Prefetch K(t+1) — overlaps softmax + P@V
        if (t < 7) {
            __nv_bfloat16* Kn = Ks + ((t + 1) & 1) * (AK_STG / 2);
#pragma unroll
            for (int i = 0; i < 4; i++) {
                const int idx = tid + i * 256;
                const int r = idx >> 3, c8 = (idx & 7) * 8;
                cp16(&Kn[r * 72 + c8], kbase + (size_t)(kb + 128 + r) * 3 * D_ + c8);
            }
            CP_COMMIT();
            CP_WAIT(1);    // V(t) complete; K(t+1) in flight
        } else {
            CP_WAIT(0);
        }
        __syncthreads();   // Vs visible to all warps

        // ---- blend with sim (L2-resident gmem) + online softmax ----
        const float* simp = sim + (size_t)(qb + wm + l8) * N_ + kb;
        float zx0 = -1e30f, zx1 = -1e30f;
#pragma unroll
        for (int ni = 0; ni < 16; ni++) {
            const float2 s0 = __ldg(reinterpret_cast<const float2*>(simp + ni * 8 + l4 * 2));
            const float2 s1 = __ldg(reinterpret_cast<const float2*>(simp + 8 * N_ + ni * 8 + l4 * 2));
            s[ni][0] = fmaf(s[ni][0], c1, s0.x * c2);
            s[ni][1] = fmaf(s[ni][1], c1, s0.y * c2);
            s[ni][2] = fmaf(s[ni][2], c1, s1.x * c2);
            s[ni][3] = fmaf(s[ni][3], c1, s1.y * c2);
            zx0 = fmaxf(zx0, fmaxf(s[ni][0], s[ni][1]));
            zx1 = fmaxf(zx1, fmaxf(s[ni][2], s[ni][3]));
        }
        zx0 = fmaxf(zx0, __shfl_xor_sync(0xffffffffu, zx0, 1));
        zx0 = fmaxf(zx0, __shfl_xor_sync(0xffffffffu, zx0, 2));
        zx1 = fmaxf(zx1, __shfl_xor_sync(0xffffffffu, zx1, 1));
        zx1 = fmaxf(zx1, __shfl_xor_sync(0xffffffffu, zx1, 2));

        const float mn0 = fmaxf(m0, zx0), mn1 = fmaxf(m1, zx1);
        const float f0 = __expf(m0 - mn0), f1 = __expf(m1 - mn1);
        m0 = mn0; m1 = mn1;

        float ls0 = 0.f, ls1 = 0.f;
        uint32_t* prow0 = reinterpret_cast<uint32_t*>(Ps + (wm + l8) * 136);
        uint32_t* prow1 = reinterpret_cast<uint32_t*>(Ps + (wm + l8 + 8) * 136);
#pragma unroll
        for (int ni = 0; ni < 16; ni++) {
            const float p0 = __expf(s[ni][0] - mn0);
            const float p1 = __expf(s[ni][1] - mn0);
            const float p2 = __expf(s[ni][2] - mn1);
            const float p3 = __expf(s[ni][3] - mn1);
            ls0 += p0 + p1; ls1 += p2 + p3;
            prow0[ni * 4 + l4] = pack_bf2(p0, p1);
            prow1[ni * 4 + l4] = pack_bf2(p2, p3);
        }
        ls0 += __shfl_xor_sync(0xffffffffu, ls0, 1);
        ls0 += __shfl_xor_sync(0xffffffffu, ls0, 2);
        ls1 += __shfl_xor_sync(0xffffffffu, ls1, 1);
        ls1 += __shfl_xor_sync(0xffffffffu, ls1, 2);
        l0 = l0 * f0 + ls0;
        l1 = l1 * f1 + ls1;

#pragma unroll
        for (int ni = 0; ni < 8; ni++) {
            o[ni][0] *= f0; o[ni][1] *= f0;
            o[ni][2] *= f1; o[ni][3] *= f1;
        }
        __syncwarp();   // P rows warp-private: order stores before ldmatrix

        // ---- O += P @ V : 8 n-frags, k = 128 (8 ksteps of 16) ----
#pragma unroll
        for (int ks = 0; ks < 128; ks += 16) {
            uint32_t a[4];
            ldsm4(a, p_ld + ks * 2);
#pragma unroll
            for (int np = 0; np < 4; np++) {
                uint32_t bb[4];
                ldsm4t(bb, v_ln + ks * 144 + np * 32);   // 144 = 72*2
                mma_bf16(o[2 * np],     a, bb);
                mma_bf16(o[2 * np + 1], a, bb + 2);
            }
        }
    }

    // Epilogue: normalize, convert to bf16, store
    const float inv0 = 1.f / l0, inv1 = 1.f / l1;
    __nv_bfloat16* op0 = att + (size_t)(b * N_ + qb + wm + l8) * D_ + h * HD_;
    __nv_bfloat16* op1 = op0 + 8 * D_;
#pragma unroll
    for (int ni = 0; ni < 8; ni++) {
        *reinterpret_cast<uint32_t*>(op0 + ni * 8 + l4 * 2)
            = pack_bf2(o[ni][0] * inv0, o[ni][1] * inv0);
        *reinterpret_cast<uint32_t*>(op1 + ni * 8 + l4 * 2)
            = pack_bf2(o[ni][2] * inv1, o[ni][3] * inv1);
    }
}

// ---------------------------------------------------------------------------
extern "C" void kernel_launch(void* const* d_in, const int* in_sizes, int n_in,
                              void* d_out, int out_size)
{
    const float* x      = (const float*)d_in[0];
    const float* gamma  = (const float*)d_in[1];
    const float* beta   = (const float*)d_in[2];
    const float* w_qkv  = (const float*)d_in[3];
    const float* w_proj = (const float*)d_in[4];
    const float* b_proj = (const float*)d_in[5];
    const float* swl    = (const float*)d_in[6];
    const float* sim    = (const float*)d_in[7];
    float* out = (float*)d_out;

    __nv_bfloat16 *xn, *qkvb, *attb, *wqb, *wpb;
    cudaGetSymbolAddress((void**)&xn,   g_xn);
    cudaGetSymbolAddress((void**)&qkvb, g_qkv);
    cudaGetSymbolAddress((void**)&attb, g_att);
    cudaGetSymbolAddress((void**)&wqb,  g_wqkv);
    cudaGetSymbolAddress((void**)&wpb,  g_wprj);

    // 0. Weight conversion fp32 -> bf16
    cvt_kernel<<<(D_ * 3 * D_ / 4 + 255) / 256, 256>>>(w_qkv, wqb, D_ * 3 * D_ / 4);
    cvt_kernel<<<(D_ * D_ / 4 + 255) / 256, 256>>>(w_proj, wpb, D_ * D_ / 4);

    // 1. LayerNorm (fp32 in, bf16 out)
    ln_kernel<<<M_, 256>>>(x, gamma, beta, xn);

    // 2. QKV projection: bf16 GEMM -> bf16 out
    bf16_gemm_kernel<3 * D_, false><<<dim3(24, 32), 256>>>(
        xn, wqb, qkvb, nullptr, nullptr);

    // 3. Attention (flash, bf16 mma, cp.async pipelined)
    cudaFuncSetAttribute(attn_bf16_kernel,
                         cudaFuncAttributeMaxDynamicSharedMemorySize,
                         ATT_SMEM_BYTES);
    attn_bf16_kernel<<<dim3(8, 64), 256, ATT_SMEM_BYTES>>>(qkvb, sim, swl, attb);

    // 4. Output projection + bias + residual -> fp32 d_out
    bf16_gemm_kernel<D_, true><<<dim3(8, 32), 256>>>(
        attb, wpb, out, b_proj, x);
}

// round 13
// speedup vs baseline: 1.8642x; 1.6700x over previous
#include <cuda_runtime.h>
#include <cuda_bf16.h>
#include <cstdint>

#define B_  4
#define N_  1024
#define D_  1024
#define H_  16
#define HD_ 64
#define M_  (B_*N_)   // 4096 token rows

// Scratch (device globals — no runtime allocation allowed)
__device__ __nv_bfloat16 g_xn  [M_ * D_];        // LN output (bf16 GEMM A)
__device__ __nv_bfloat16 g_qkv [M_ * 3 * D_];    // QKV output (bf16)
__device__ __nv_bfloat16 g_att [M_ * D_];        // attention output (bf16)
__device__ __nv_bfloat16 g_wqkv[D_ * 3 * D_];    // w_qkv bf16
__device__ __nv_bfloat16 g_wprj[D_ * D_];        // w_proj bf16

// ---------------------------------------------------------------------------
// Helpers
// ---------------------------------------------------------------------------
__device__ __forceinline__ void mma_bf16(float* c, const uint32_t* a, const uint32_t* b) {
    asm volatile(
        "mma.sync.aligned.m16n8k16.row.col.f32.bf16.bf16.f32 "
        "{%0,%1,%2,%3}, {%4,%5,%6,%7}, {%8,%9}, {%0,%1,%2,%3};\n"
        : "+f"(c[0]), "+f"(c[1]), "+f"(c[2]), "+f"(c[3])
        : "r"(a[0]), "r"(a[1]), "r"(a[2]), "r"(a[3]), "r"(b[0]), "r"(b[1]));
}

__device__ __forceinline__ void ldsm4(uint32_t* r, uint32_t saddr) {
    asm volatile("ldmatrix.sync.aligned.m8n8.x4.shared.b16 {%0,%1,%2,%3}, [%4];\n"
        : "=r"(r[0]), "=r"(r[1]), "=r"(r[2]), "=r"(r[3]) : "r"(saddr));
}
__device__ __forceinline__ void ldsm4t(uint32_t* r, uint32_t saddr) {
    asm volatile("ldmatrix.sync.aligned.m8n8.x4.trans.shared.b16 {%0,%1,%2,%3}, [%4];\n"
        : "=r"(r[0]), "=r"(r[1]), "=r"(r[2]), "=r"(r[3]) : "r"(saddr));
}

__device__ __forceinline__ void cp16(void* smem_dst, const void* gmem_src) {
    const uint32_t s = (uint32_t)__cvta_generic_to_shared(smem_dst);
    asm volatile("cp.async.cg.shared.global [%0], [%1], 16;\n" :: "r"(s), "l"(gmem_src));
}
#define CP_COMMIT() asm volatile("cp.async.commit_group;\n" ::: "memory")
#define CP_WAIT(n)  asm volatile("cp.async.wait_group %0;\n" :: "n"(n) : "memory")

__device__ __forceinline__ uint32_t pack_bf2(float a, float b) {
    __nv_bfloat162 h = __float22bfloat162_rn(make_float2(a, b));
    return *reinterpret_cast<uint32_t*>(&h);
}

// ---------------------------------------------------------------------------
// fp32 -> bf16 weight conversion (grid-stride over float4)
// ---------------------------------------------------------------------------
__global__ __launch_bounds__(256) void cvt_kernel(
    const float* __restrict__ src, __nv_bfloat16* __restrict__ dst, int n4)
{
    const int i = blockIdx.x * blockDim.x + threadIdx.x;
    if (i < n4) {
        const float4 v = reinterpret_cast<const float4*>(src)[i];
        uint2 u;
        u.x = pack_bf2(v.x, v.y);
        u.y = pack_bf2(v.z, v.w);
        reinterpret_cast<uint2*>(dst)[i] = u;
    }
}

// ---------------------------------------------------------------------------
// LayerNorm: one block per row, 256 threads, float4 in -> bf16x4 out
// ---------------------------------------------------------------------------
__global__ __launch_bounds__(256) void ln_kernel(
    const float* __restrict__ x, const float* __restrict__ gamma,
    const float* __restrict__ beta, __nv_bfloat16* __restrict__ out)
{
    const int row = blockIdx.x;
    const int tid = threadIdx.x;
    const float4 v = reinterpret_cast<const float4*>(x)[row * (D_ / 4) + tid];

    __shared__ float red[8];
    float s = v.x + v.y + v.z + v.w;
#pragma unroll
    for (int o = 16; o > 0; o >>= 1) s += __shfl_xor_sync(0xffffffffu, s, o);
    if ((tid & 31) == 0) red[tid >> 5] = s;
    __syncthreads();
    float tot = 0.f;
#pragma unroll
    for (int i = 0; i < 8; i++) tot += red[i];
    const float mean = tot * (1.0f / D_);

    const float d0 = v.x - mean, d1 = v.y - mean, d2 = v.z - mean, d3 = v.w - mean;
    float sq = d0 * d0 + d1 * d1 + d2 * d2 + d3 * d3;
    __syncthreads();
#pragma unroll
    for (int o = 16; o > 0; o >>= 1) sq += __shfl_xor_sync(0xffffffffu, sq, o);
    if ((tid & 31) == 0) red[tid >> 5] = sq;
    __syncthreads();
    float vt = 0.f;
#pragma unroll
    for (int i = 0; i < 8; i++) vt += red[i];
    const float rstd = rsqrtf(vt * (1.0f / D_) + 1e-5f);

    const float4 g = reinterpret_cast<const float4*>(gamma)[tid];
    const float4 b = reinterpret_cast<const float4*>(beta)[tid];
    uint2 u;
    u.x = pack_bf2(d0 * rstd * g.x + b.x, d1 * rstd * g.y + b.y);
    u.y = pack_bf2(d2 * rstd * g.z + b.z, d3 * rstd * g.w + b.w);
    reinterpret_cast<uint2*>(out)[row * (D_ / 4) + tid] = u;
}

// ---------------------------------------------------------------------------
// BF16 tensor-core GEMM, cp.async double buffer (unchanged from R12).
// C[M_, NC] = A[M_, 1024] @ W[1024, NC], A/W bf16.
// ---------------------------------------------------------------------------
#define GA_PITCH 40
#define GB_PITCH 136
#define GA_STG_BYTES (128 * GA_PITCH * 2)   // 10240
#define GB_STG_BYTES (32 * GB_PITCH * 2)    // 8704

template <int NC, bool PROJ>
__global__ __launch_bounds__(256) void bf16_gemm_kernel(
    const __nv_bfloat16* __restrict__ A, const __nv_bfloat16* __restrict__ W,
    void* __restrict__ Cv, const float* __restrict__ bias,
    const float* __restrict__ resid)
{
    __shared__ __nv_bfloat16 As[2][128 * GA_PITCH];
    __shared__ __nv_bfloat16 Bs[2][32 * GB_PITCH];

    const int tid  = threadIdx.x;
    const int lane = tid & 31;
    const int warp = tid >> 5;
    const int wm = (warp >> 2) * 64;
    const int wn = (warp & 3) * 32;
    const int l4 = lane & 3, l8 = lane >> 2;

    const int rb = blockIdx.y * 128;
    const int cb = blockIdx.x * 128;

    const uint32_t as_b = (uint32_t)__cvta_generic_to_shared(&As[0][0]);
    const uint32_t bs_b = (uint32_t)__cvta_generic_to_shared(&Bs[0][0]);
    uint32_t a_addr[4];
#pragma unroll
    for (int mi = 0; mi < 4; mi++)
        a_addr[mi] = as_b + ((wm + mi * 16 + (lane & 15)) * GA_PITCH
                             + ((lane >> 4) & 1) * 8) * 2;
    const uint32_t b_addr = bs_b
        + ((((lane & 7) + ((lane >> 3) & 1) * 8)) * GB_PITCH
           + ((lane >> 4) & 1) * 8 + wn) * 2;

    float c[4][4][4];
#pragma unroll
    for (int mi = 0; mi < 4; mi++)
#pragma unroll
        for (int ni = 0; ni < 4; ni++)
#pragma unroll
            for (int j = 0; j < 4; j++) c[mi][ni][j] = 0.f;

    auto issue_tile = [&](int k0, int st) {
#pragma unroll
        for (int i = 0; i < 2; i++) {
            const int f = tid + i * 256;          // 512 16B chunks each
            cp16(&As[st][(f >> 2) * GA_PITCH + (f & 3) * 8],
                 A + (size_t)(rb + (f >> 2)) * D_ + k0 + (f & 3) * 8);
            cp16(&Bs[st][(f >> 4) * GB_PITCH + (f & 15) * 8],
                 W + (size_t)(k0 + (f >> 4)) * NC + cb + (f & 15) * 8);
        }
        CP_COMMIT();
    };

    issue_tile(0, 0);
    for (int it = 0; it < 32; ++it) {
        const int buf = it & 1;
        if (it < 31) { issue_tile((it + 1) * 32, buf ^ 1); CP_WAIT(1); }
        else         { CP_WAIT(0); }
        __syncthreads();

        const uint32_t ao = (uint32_t)buf * GA_STG_BYTES;
        const uint32_t bo = (uint32_t)buf * GB_STG_BYTES;
#pragma unroll
        for (int ks = 0; ks < 32; ks += 16) {
            uint32_t a[4][4], bb[2][4];
#pragma unroll
            for (int mi = 0; mi < 4; mi++)
                ldsm4(a[mi], a_addr[mi] + ao + ks * 2);
#pragma unroll
            for (int np = 0; np < 2; np++)
                ldsm4t(bb[np], b_addr + bo + ks * (GB_PITCH * 2) + np * 32);
#pragma unroll
            for (int mi = 0; mi < 4; mi++)
#pragma unroll
                for (int np = 0; np < 2; np++) {
                    mma_bf16(c[mi][2 * np],     a[mi], bb[np]);
                    mma_bf16(c[mi][2 * np + 1], a[mi], bb[np] + 2);
                }
        }
        __syncthreads();
    }

#pragma unroll
    for (int mi = 0; mi < 4; mi++) {
        const int r0 = rb + wm + mi * 16 + l8;
#pragma unroll
        for (int ni = 0; ni < 4; ni++) {
            const int col = cb + wn + ni * 8 + l4 * 2;
            if (PROJ) {
                float* C = (float*)Cv;
                float2 v0 = {c[mi][ni][0], c[mi][ni][1]};
                float2 v1 = {c[mi][ni][2], c[mi][ni][3]};
                const float2 bz = *reinterpret_cast<const float2*>(bias + col);
                const float2 r0x = *reinterpret_cast<const float2*>(resid + (size_t)r0 * D_ + col);
                const float2 r1x = *reinterpret_cast<const float2*>(resid + (size_t)(r0 + 8) * D_ + col);
                v0.x += bz.x + r0x.x; v0.y += bz.y + r0x.y;
                v1.x += bz.x + r1x.x; v1.y += bz.y + r1x.y;
                *reinterpret_cast<float2*>(C + (size_t)r0 * NC + col) = v0;
                *reinterpret_cast<float2*>(C + (size_t)(r0 + 8) * NC + col) = v1;
            } else {
                __nv_bfloat16* C = (__nv_bfloat16*)Cv;
                *reinterpret_cast<uint32_t*>(C + (size_t)r0 * NC + col)
                    = pack_bf2(c[mi][ni][0], c[mi][ni][1]);
                *reinterpret_cast<uint32_t*>(C + (size_t)(r0 + 8) * NC + col)
                    = pack_bf2(c[mi][ni][2], c[mi][ni][3]);
            }
        }
    }
}

// ---------------------------------------------------------------------------
// BF16 mma flash attention, occupancy 2, register-resident P.
// Key identity: m16n8k16 A-fragment == two adjacent m16n8 C-fragments
// (a0..a3 = (r,k0),(r+8,k0),(r,k0+8),(r+8,k0+8) = c0..c3 of S-frags 2j,2j+1),
// so P feeds the P@V mma straight from registers — no P smem at all.
// Smem: Qs [128][72] @0 | Ks 2x[128][72] @18432 | Vs [128][72] @55296 = 73728 B
// -> 2 CTAs/SM (147 KB), __launch_bounds__(256,2) caps regs at 128.
// ---------------------------------------------------------------------------
#define AQ_BYTE 0
#define AK_BYTE 18432
#define AK_STG  18432
#define AV_BYTE 55296
#define ATT_SMEM_BYTES 73728

__global__ __launch_bounds__(256, 2) void attn_bf16_kernel(
    const __nv_bfloat16* __restrict__ qkv, const float* __restrict__ sim,
    const float* __restrict__ swlp, __nv_bfloat16* __restrict__ att)
{
    extern __shared__ char smc[];
    __nv_bfloat16* Qs = (__nv_bfloat16*)(smc + AQ_BYTE);   // pitch 72
    __nv_bfloat16* Ks = (__nv_bfloat16*)(smc + AK_BYTE);   // pitch 72, 2 stages
    __nv_bfloat16* Vs = (__nv_bfloat16*)(smc + AV_BYTE);   // pitch 72

    const int tid  = threadIdx.x;
    const int lane = tid & 31, warp = tid >> 5;
    const int l4 = lane & 3, l8 = lane >> 2;
    const int wm = warp * 16;
    const int qb = blockIdx.x * 128;
    const int b  = blockIdx.y >> 4, h = blockIdx.y & 15;

    const float alpha = 1.f / (1.f + __expf(-(*swlp)));
    const float c1 = (1.f - alpha) * 0.125f;
    const float c2 = alpha;

    const __nv_bfloat16* qp    = qkv + (size_t)(b * N_ + qb) * 3 * D_ + h * HD_;
    const __nv_bfloat16* kbase = qkv + (size_t)(b * N_) * 3 * D_ + D_ + h * HD_;
    const __nv_bfloat16* vbase = qkv + (size_t)(b * N_) * 3 * D_ + 2 * D_ + h * HD_;

    // ldmatrix lane addresses (bytes)
    const uint32_t smb = (uint32_t)__cvta_generic_to_shared(smc);
    const uint32_t q_ld = smb + AQ_BYTE
        + ((wm + (lane & 15)) * 72 + ((lane >> 4) & 1) * 8) * 2;
    const uint32_t k_ln = smb + AK_BYTE
        + ((((lane >> 4) & 1) * 8 + (lane & 7)) * 72 + ((lane >> 3) & 1) * 8) * 2;
    const uint32_t v_ln = smb + AV_BYTE
        + (((lane & 7) + ((lane >> 3) & 1) * 8) * 72 + ((lane >> 4) & 1) * 8) * 2;

    // Prologue: Q tile + K(0) via cp.async (one group). 128B/row = 8 chunks.
#pragma unroll
    for (int i = 0; i < 4; i++) {
        const int idx = tid + i * 256;            // 1024 chunks
        const int r = idx >> 3, c8 = (idx & 7) * 8;
        cp16(&Qs[r * 72 + c8], qp + (size_t)r * 3 * D_ + c8);
        cp16(&Ks[r * 72 + c8], kbase + (size_t)r * 3 * D_ + c8);
    }
    CP_COMMIT();

    float o[8][4];
#pragma unroll
    for (int ni = 0; ni < 8; ni++)
#pragma unroll
        for (int j = 0; j < 4; j++) o[ni][j] = 0.f;
    float m0 = -1e30f, m1 = -1e30f, l0 = 0.f, l1 = 0.f;

    for (int t = 0; t < 8; t++) {
        const int kb = t * 128;
        const uint32_t kst = k_ln + (t & 1) * AK_STG;

        __syncthreads();   // all warps done with Vs (prev P@V)

        // Issue V(t) — overlaps with S-mma below
#pragma unroll
        for (int i = 0; i < 4; i++) {
            const int idx = tid + i * 256;
            const int r = idx >> 3, c8 = (idx & 7) * 8;
            cp16(&Vs[r * 72 + c8], vbase + (size_t)(kb + r) * 3 * D_ + c8);
        }
        CP_COMMIT();

        CP_WAIT(1);        // K(t) [+Q] complete; V(t) still in flight
        __syncthreads();

        // ---- S = Q @ K^T : 16 n-frags, k = 64 (4 ksteps of 16) ----
        float s[16][4];
#pragma unroll
        for (int ni = 0; ni < 16; ni++)
#pragma unroll
            for (int j = 0; j < 4; j++) s[ni][j] = 0.f;
#pragma unroll
        for (int ks = 0; ks < 64; ks += 16) {
            uint32_t a[4];
            ldsm4(a, q_ld + ks * 2);
#pragma unroll
            for (int j = 0; j < 8; j++) {
                uint32_t bb[4];
                ldsm4(bb, kst + j * 2304 + ks * 2);   // 2304 = 16*72*2
                mma_bf16(s[2 * j],     a, bb);
                mma_bf16(s[2 * j + 1], a, bb + 2);
            }
        }

        // Prefetch K(t+1) — overlaps softmax + P@V
        if (t < 7) {
            __nv_bfloat16* Kn = Ks + ((t + 1) & 1) * (AK_STG / 2);
#pragma unroll
            for (int i = 0; i < 4; i++) {
                const int idx = tid + i * 256;
                const int r = idx >> 3, c8 = (idx & 7) * 8;
                cp16(&Kn[r * 72 + c8], kbase + (size_t)(kb + 128 + r) * 3 * D_ + c8);
            }
            CP_COMMIT();
            CP_WAIT(1);    // V(t) complete; K(t+1) in flight
        } else {
            CP_WAIT(0);
        }
        __syncthreads();   // Vs visible to all warps

        // ---- blend with sim (L2-resident gmem) + online softmax ----
        const float* simp = sim + (size_t)(qb + wm + l8) * N_ + kb;
        float zx0 = -1e30f, zx1 = -1e30f;
#pragma unroll
        for (int ni = 0; ni < 16; ni++) {
            const float2 s0 = __ldg(reinterpret_cast<const float2*>(simp + ni * 8 + l4 * 2));
            const float2 s1 = __ldg(reinterpret_cast<const float2*>(simp + 8 * N_ + ni * 8 + l4 * 2));
            s[ni][0] = fmaf(s[ni][0], c1, s0.x * c2);
            s[ni][1] = fmaf(s[ni][1], c1, s0.y * c2);
            s[ni][2] = fmaf(s[ni][2], c1, s1.x * c2);
            s[ni][3] = fmaf(s[ni][3], c1, s1.y * c2);
            zx0 = fmaxf(zx0, fmaxf(s[ni][0], s[ni][1]));
            zx1 = fmaxf(zx1, fmaxf(s[ni][2], s[ni][3]));
        }
        zx0 = fmaxf(zx0, __shfl_xor_sync(0xffffffffu, zx0, 1));
        zx0 = fmaxf(zx0, __shfl_xor_sync(0xffffffffu, zx0, 2));
        zx1 = fmaxf(zx1, __shfl_xor_sync(0xffffffffu, zx1, 1));
        zx1 = fmaxf(zx1, __shfl_xor_sync(0xffffffffu, zx1, 2));

        const float mn0 = fmaxf(m0, zx0), mn1 = fmaxf(m1, zx1);
        const float f0 = __expf(m0 - mn0), f1 = __expf(m1 - mn1);
        m0 = mn0; m1 = mn1;

        // P stays in registers: pa[j] is the ready-made A-fragment for P@V.
        float ls0 = 0.f, ls1 = 0.f;
        uint32_t pa[8][4];
#pragma unroll
        for (int j = 0; j < 8; j++) {
            const float p00 = __expf(s[2 * j][0] - mn0);
            const float p01 = __expf(s[2 * j][1] - mn0);
            const float p02 = __expf(s[2 * j][2] - mn1);
            const float p03 = __expf(s[2 * j][3] - mn1);
            const float p10 = __expf(s[2 * j + 1][0] - mn0);
            const float p11 = __expf(s[2 * j + 1][1] - mn0);
            const float p12 = __expf(s[2 * j + 1][2] - mn1);
            const float p13 = __expf(s[2 * j + 1][3] - mn1);
            ls0 += p00 + p01 + p10 + p11;
            ls1 += p02 + p03 + p12 + p13;
            pa[j][0] = pack_bf2(p00, p01);   // (r,   k0)
            pa[j][1] = pack_bf2(p02, p03);   // (r+8, k0)
            pa[j][2] = pack_bf2(p10, p11);   // (r,   k0+8)
            pa[j][3] = pack_bf2(p12, p13);   // (r+8, k0+8)
        }
        ls0 += __shfl_xor_sync(0xffffffffu, ls0, 1);
        ls0 += __shfl_xor_sync(0xffffffffu, ls0, 2);
        ls1 += __shfl_xor_sync(0xffffffffu, ls1, 1);
        ls1 += __shfl_xor_sync(0xffffffffu, ls1, 2);
        l0 = l0 * f0 + ls0;
        l1 = l1 * f1 + ls1;

#pragma unroll
        for (int ni = 0; ni < 8; ni++) {
            o[ni][0] *= f0; o[ni][1] *= f0;
            o[ni][2] *= f1; o[ni][3] *= f1;
        }

        // ---- O += P @ V : 8 n-frags, k = 128 (8 ksteps of 16) ----
#pragma unroll
        for (int j = 0; j < 8; j++) {
#pragma unroll
            for (int np = 0; np < 4; np++) {
                uint32_t bb[4];
                ldsm4t(bb, v_ln + j * 2304 + np * 32);   // 2304 = 16*72*2
                mma_bf16(o[2 * np],     pa[j], bb);
                mma_bf16(o[2 * np + 1], pa[j], bb + 2);
            }
        }
    }

    // Epilogue: normalize, convert to bf16, store
    const float inv0 = 1.f / l0, inv1 = 1.f / l1;
    __nv_bfloat16* op0 = att + (size_t)(b * N_ + qb + wm + l8) * D_ + h * HD_;
    __nv_bfloat16* op1 = op0 + 8 * D_;
#pragma unroll
    for (int ni = 0; ni < 8; ni++) {
        *reinterpret_cast<uint32_t*>(op0 + ni * 8 + l4 * 2)
            = pack_bf2(o[ni][0] * inv0, o[ni][1] * inv0);
        *reinterpret_cast<uint32_t*>(op1 + ni * 8 + l4 * 2)
            = pack_bf2(o[ni][2] * inv1, o[ni][3] * inv1);
    }
}

// ---------------------------------------------------------------------------
extern "C" void kernel_launch(void* const* d_in, const int* in_sizes, int n_in,
                              void* d_out, int out_size)
{
    const float* x      = (const float*)d_in[0];
    const float* gamma  = (const float*)d_in[1];
    const float* beta   = (const float*)d_in[2];
    const float* w_qkv  = (const float*)d_in[3];
    const float* w_proj = (const float*)d_in[4];
    const float* b_proj = (const float*)d_in[5];
    const float* swl    = (const float*)d_in[6];
    const float* sim    = (const float*)d_in[7];
    float* out = (float*)d_out;

    __nv_bfloat16 *xn, *qkvb, *attb, *wqb, *wpb;
    cudaGetSymbolAddress((void**)&xn,   g_xn);
    cudaGetSymbolAddress((void**)&qkvb, g_qkv);
    cudaGetSymbolAddress((void**)&attb, g_att);
    cudaGetSymbolAddress((void**)&wqb,  g_wqkv);
    cudaGetSymbolAddress((void**)&wpb,  g_wprj);

    // 0. Weight conversion fp32 -> bf16
    cvt_kernel<<<(D_ * 3 * D_ / 4 + 255) / 256, 256>>>(w_qkv, wqb, D_ * 3 * D_ / 4);
    cvt_kernel<<<(D_ * D_ / 4 + 255) / 256, 256>>>(w_proj, wpb, D_ * D_ / 4);

    // 1. LayerNorm (fp32 in, bf16 out)
    ln_kernel<<<M_, 256>>>(x, gamma, beta, xn);

    // 2. QKV projection: bf16 GEMM -> bf16 out
    bf16_gemm_kernel<3 * D_, false><<<dim3(24, 32), 256>>>(
        xn, wqb, qkvb, nullptr, nullptr);

    // 3. Attention (flash, bf16 mma, occ 2, register-resident P)
    cudaFuncSetAttribute(attn_bf16_kernel,
                         cudaFuncAttributeMaxDynamicSharedMemorySize,
                         ATT_SMEM_BYTES);
    attn_bf16_kernel<<<dim3(8, 64), 256, ATT_SMEM_BYTES>>>(qkvb, sim, swl, attb);

    // 4. Output projection + bias + residual -> fp32 d_out
    bf16_gemm_kernel<D_, true><<<dim3(8, 32), 256>>>(
        attb, wpb, out, b_proj, x);
}